// round 16
// baseline (speedup 1.0000x reference)
#include <cuda_runtime.h>
#include <cuda_bf16.h>
#include <cstdint>

// Per-pixel dynamic 5x5 conv, channel-shared taps.
// x: [B=8, C=64, H=256, W=256] f32; w: [25, B, 1, H, W] f32
//
// Warp-private cp.async pipelines (8-slab ring, stage 6 channels ahead),
// 2x2 quad/thread, parity-split FFMA2/FFMA, 3 CTAs/SM. This round: the two
// channels per iteration are FUSED into one row loop (6 LDS then A-FMAs then
// B-FMAs per row) so every LDS has ~28 independent FMAs of latency cover;
// packed accumulator chains merged (2 per channel) to keep regs <= 170.
// Output stores use .cs (streaming) to preserve L2 for x halos.

#define BB 8
#define HW 65536
#define HH_DIM 256
#define WW_DIM 256
#define TW 32
#define SMW 40                 // slab row stride (floats)
#define WROWS 8                // rows per warp slab (4 out + 4 halo)
#define WSTAGE (WROWS * SMW)   // 320 floats = 1280 B per slab
#define SLAB_B (WSTAGE * 4)
#define NSLOT4 80              // float4 slots per slab
#define CPERCTA 32
#define NSTAGE 8               // slabs in the per-warp ring

__device__ __forceinline__ void cp_async16(uint32_t saddr, const void* gaddr, int src_size) {
    asm volatile("cp.async.cg.shared.global [%0], [%1], 16, %2;"
                 :: "r"(saddr), "l"(gaddr), "r"(src_size));
}
__device__ __forceinline__ void cp_commit() {
    asm volatile("cp.async.commit_group;");
}
template <int N>
__device__ __forceinline__ void cp_wait() {
    asm volatile("cp.async.wait_group %0;" :: "n"(N));
}

__device__ __forceinline__ uint64_t lds64(uint32_t a) {
    uint64_t v; asm volatile("ld.shared.b64 %0, [%1];" : "=l"(v) : "r"(a)); return v;
}
__device__ __forceinline__ void ffma2(uint64_t& d, uint64_t a, uint64_t b) {
    asm("fma.rn.f32x2 %0, %1, %2, %0;" : "+l"(d) : "l"(a), "l"(b));
}
__device__ __forceinline__ void unpack2f(uint64_t v, float& lo, float& hi) {
    asm("mov.b64 {%0, %1}, %2;" : "=f"(lo), "=f"(hi) : "l"(v));
}
__device__ __forceinline__ float lo_f(uint64_t v) { float a, b; unpack2f(v, a, b); return a; }
__device__ __forceinline__ float hi_f(uint64_t v) { float a, b; unpack2f(v, a, b); return b; }
__device__ __forceinline__ void stcs2(float* p, float a, float b) {
    asm volatile("st.global.cs.v2.f32 [%0], {%1, %2};" :: "l"(p), "f"(a), "f"(b) : "memory");
}

__global__ __launch_bounds__(128, 3)
void dynconv5x5_kernel(const float* __restrict__ x,
                       const float* __restrict__ wgt,
                       float* __restrict__ out) {
    __shared__ float sm[4][NSTAGE][WSTAGE];   // 40 KB: [warp][slab][data]

    const int tid  = threadIdx.x;
    const int wid  = tid >> 5;
    const int lane = tid & 31;
    const int qx   = lane & 15;
    const int qy   = lane >> 4;
    const int w0   = blockIdx.x * TW;
    const int h0   = blockIdx.y * 16;
    const int z    = blockIdx.z;
    const int b    = z >> 1;
    const int c0   = (z & 1) * CPERCTA;

    const int slab0 = h0 + wid * 4;
    const int oh    = slab0 + qy * 2;
    const int ow    = w0 + qx * 2;

    // ---- weights, parity-split (100 regs)
    uint64_t wtp[15], wbp[15];
    float wtsl[10], wtsh[10], wbsl[10], wbsh[10];
#pragma unroll
    for (int r = 0; r < 5; r++) {
#pragma unroll
        for (int ww = 0; ww < 5; ww++) {
            const float* wp = &wgt[(((size_t)(r * 5 + ww) * BB + b) * HH_DIM + oh) * WW_DIM + ow];
            uint64_t t  = *(const uint64_t*)(wp);
            uint64_t bo = *(const uint64_t*)(wp + WW_DIM);
            if ((ww & 1) == 0) {
                wtp[r * 3 + ww / 2] = t;
                wbp[r * 3 + ww / 2] = bo;
            } else {
                int j = r * 2 + (ww == 3);
                unpack2f(t,  wtsl[j], wtsh[j]);
                unpack2f(bo, wbsl[j], wbsh[j]);
            }
        }
    }

    // ---- 16B staging slots (80 float4 = 8 rows x 10; col c <-> gw w0-4+c)
    int xoff[3];
    int ssz [3];
    int soff[3];
    const bool has3 = (lane < 16);
#pragma unroll
    for (int j = 0; j < 3; j++) {
        int i    = lane + j * 32;
        int r    = i / 10;
        int col4 = i - r * 10;
        int gh = slab0 + r - 2;
        int gw = w0 - 4 + col4 * 4;
        bool v = (i < NSLOT4) && gh >= 0 && gh < HH_DIM && gw >= 0 && gw < WW_DIM;
        xoff[j] = gh * WW_DIM + gw;
        ssz[j]  = v ? 16 : 0;
        soff[j] = (r * SMW + col4 * 4) * 4;
    }

    const float* xc = x   + ((size_t)b * 64 + c0) * HW;
    float*       ob = out + (((size_t)b * 64 + c0) * HW) + oh * WW_DIM + ow;

    const uint32_t wbase = (uint32_t)__cvta_generic_to_shared(&sm[wid][0][0]);
    const uint32_t cbase = wbase + ((qy * 2) * SMW + (qx * 2 + 2)) * 4;

    // ---- prologue: stage channels 0..5 into slabs 0..5
#pragma unroll
    for (int p = 0; p < 6; p++) {
        const float* xp = xc + (size_t)p * HW;
        const uint32_t sp = wbase + p * SLAB_B;
        cp_async16(sp + soff[0], xp + xoff[0], ssz[0]);
        cp_async16(sp + soff[1], xp + xoff[1], ssz[1]);
        if (has3) cp_async16(sp + soff[2], xp + xoff[2], ssz[2]);
        cp_commit();
    }

#pragma unroll 2
    for (int it = 0; it < CPERCTA / 2; it++) {
        const int cA = 2 * it;
        const int cB = cA + 1;

        if (cA + 6 < CPERCTA) cp_wait<4>(); else cp_wait<0>();
        __syncwarp(0xffffffffu);

        const uint32_t bA = cbase + (cA & 7) * SLAB_B;
        const uint32_t bB = cbase + (cB & 7) * SLAB_B;

        // fused accumulators: 1 packed chain per pixel row per channel
        uint64_t atA = 0, abA = 0, atB = 0, abB = 0;
        float tA0 = 0.f, tA1 = 0.f, bA0 = 0.f, bA1 = 0.f;
        float tB0 = 0.f, tB1 = 0.f, bB0 = 0.f, bB1 = 0.f;

#pragma unroll
        for (int r = 0; r < 6; r++) {
            const uint32_t oA = bA + r * (SMW * 4);
            const uint32_t oB = bB + r * (SMW * 4);
            uint64_t pA0 = lds64(oA);
            uint64_t pA2 = lds64(oA + 8);
            uint64_t pA4 = lds64(oA + 16);
            uint64_t pB0 = lds64(oB);
            uint64_t pB2 = lds64(oB + 8);
            uint64_t pB4 = lds64(oB + 16);

            float xA1 = hi_f(pA0), xA2 = lo_f(pA2), xA3 = hi_f(pA2), xA4 = lo_f(pA4);
            float xB1 = hi_f(pB0), xB2 = lo_f(pB2), xB3 = hi_f(pB2), xB4 = lo_f(pB4);

            if (r < 5) {
                ffma2(atA, pA0, wtp[r * 3 + 0]);
                ffma2(atA, pA2, wtp[r * 3 + 1]);
                ffma2(atA, pA4, wtp[r * 3 + 2]);
                tA0 = fmaf(xA1, wtsl[r * 2 + 0], tA0);
                tA1 = fmaf(xA2, wtsh[r * 2 + 0], tA1);
                tA0 = fmaf(xA3, wtsl[r * 2 + 1], tA0);
                tA1 = fmaf(xA4, wtsh[r * 2 + 1], tA1);

                ffma2(atB, pB0, wtp[r * 3 + 0]);
                ffma2(atB, pB2, wtp[r * 3 + 1]);
                ffma2(atB, pB4, wtp[r * 3 + 2]);
                tB0 = fmaf(xB1, wtsl[r * 2 + 0], tB0);
                tB1 = fmaf(xB2, wtsh[r * 2 + 0], tB1);
                tB0 = fmaf(xB3, wtsl[r * 2 + 1], tB0);
                tB1 = fmaf(xB4, wtsh[r * 2 + 1], tB1);
            }
            if (r >= 1) {
                int q = r - 1;
                ffma2(abA, pA0, wbp[q * 3 + 0]);
                ffma2(abA, pA2, wbp[q * 3 + 1]);
                ffma2(abA, pA4, wbp[q * 3 + 2]);
                bA0 = fmaf(xA1, wbsl[q * 2 + 0], bA0);
                bA1 = fmaf(xA2, wbsh[q * 2 + 0], bA1);
                bA0 = fmaf(xA3, wbsl[q * 2 + 1], bA0);
                bA1 = fmaf(xA4, wbsh[q * 2 + 1], bA1);

                ffma2(abB, pB0, wbp[q * 3 + 0]);
                ffma2(abB, pB2, wbp[q * 3 + 1]);
                ffma2(abB, pB4, wbp[q * 3 + 2]);
                bB0 = fmaf(xB1, wbsl[q * 2 + 0], bB0);
                bB1 = fmaf(xB2, wbsh[q * 2 + 0], bB1);
                bB0 = fmaf(xB3, wbsl[q * 2 + 1], bB0);
                bB1 = fmaf(xB4, wbsh[q * 2 + 1], bB1);
            }
        }

        // epilogue: combine packed + scalar chains, streaming stores
        {
            float l, h;
            float* oA = ob + (size_t)cA * HW;
            float* oB = ob + (size_t)cB * HW;
            unpack2f(atA, l, h); stcs2(oA,          l + tA0, h + tA1);
            unpack2f(abA, l, h); stcs2(oA + WW_DIM, l + bA0, h + bA1);
            unpack2f(atB, l, h); stcs2(oB,          l + tB0, h + tB1);
            unpack2f(abB, l, h); stcs2(oB + WW_DIM, l + bB0, h + bB1);
        }

        // stage channels cA+6, cB+6 (overwrite slabs last read 3 iters ago)
        if (cA + 6 < CPERCTA) {
#pragma unroll
            for (int u = 0; u < 2; u++) {
                int cs = cA + 6 + u;
                const float* xs = xc + (size_t)cs * HW;
                const uint32_t sp = wbase + (cs & 7) * SLAB_B;
                cp_async16(sp + soff[0], xs + xoff[0], ssz[0]);
                cp_async16(sp + soff[1], xs + xoff[1], ssz[1]);
                if (has3) cp_async16(sp + soff[2], xs + xoff[2], ssz[2]);
                cp_commit();
            }
        }
    }
}

extern "C" void kernel_launch(void* const* d_in, const int* in_sizes, int n_in,
                              void* d_out, int out_size) {
    const float* x   = (const float*)d_in[0];
    const float* wgt = (const float*)d_in[1];
    float*       out = (float*)d_out;

    dim3 grid(WW_DIM / TW, HH_DIM / 16, BB * 2);   // 2048 blocks
    dim3 block(128);
    dynconv5x5_kernel<<<grid, block>>>(x, wgt, out);
}